// round 1
// baseline (speedup 1.0000x reference)
#include <cuda_runtime.h>
#include <math.h>

#define NNODES 100000
#define NEDGES 1600000
#define ETOT   (NEDGES + NNODES)
#define FDIM   128

// ---------------- scratch (static device allocations) ----------------
__device__ float g_h[NNODES * FDIM];     // GEMM output (per layer)
__device__ float g_feat[NNODES * FDIM];  // layer-1 activations (input to layer 2)
__device__ float g_agg[NNODES * FDIM];   // aggregation accumulator (layer 1)
__device__ float g_as[NNODES * 4];       // alpha_src per node/head
__device__ float g_ad[NNODES * 4];       // alpha_dst per node/head
__device__ float g_m[NNODES * 4];        // segment max
__device__ float g_den[NNODES * 4];      // segment sum of exp
__device__ float g_ee[(size_t)ETOT * 4]; // exp(e - m) per edge/head

// ---------------- helpers ----------------
__device__ __forceinline__ void atomicMaxF(float* addr, float value) {
    if (value >= 0.0f) atomicMax((int*)addr, __float_as_int(value));
    else               atomicMin((unsigned int*)addr, __float_as_uint(value));
}

// ---------------- GEMM: out[M,128] = A[M,128] @ W[128,128] ----------------
// BM=64 rows/block, 256 threads, each thread computes 8 rows x 4 cols.
// A tile staged in shared (32KB); W streamed from global (L1 persists within launch).
__global__ void gemm128_kernel(const float* __restrict__ A,
                               const float* __restrict__ W,
                               float* __restrict__ out, int M) {
    __shared__ float As[64 * 128];
    int tid  = threadIdx.x;
    int row0 = blockIdx.x * 64;

    // load A tile: 64 rows x 128 = 2048 float4, 8 per thread
    #pragma unroll
    for (int i = 0; i < 8; i++) {
        int idx = tid + 256 * i;          // float4 index within tile
        int r   = idx >> 5;               // row within tile (32 float4 per row)
        float4 v = make_float4(0.f, 0.f, 0.f, 0.f);
        if (row0 + r < M) v = ((const float4*)A)[(size_t)row0 * 32 + idx];
        ((float4*)As)[idx] = v;
    }
    __syncthreads();

    int tx = tid & 31;   // column group: cols [tx*4, tx*4+3]
    int ty = tid >> 5;   // row group: rows [ty*8, ty*8+7]
    const float* Asr = As + ty * 8 * 128;

    float acc[8][4];
    #pragma unroll
    for (int r = 0; r < 8; r++)
        #pragma unroll
        for (int c = 0; c < 4; c++) acc[r][c] = 0.f;

    for (int k = 0; k < 128; k += 4) {
        float4 w0 = __ldg(&((const float4*)(W + (k + 0) * 128))[tx]);
        float4 w1 = __ldg(&((const float4*)(W + (k + 1) * 128))[tx]);
        float4 w2 = __ldg(&((const float4*)(W + (k + 2) * 128))[tx]);
        float4 w3 = __ldg(&((const float4*)(W + (k + 3) * 128))[tx]);
        #pragma unroll
        for (int r = 0; r < 8; r++) {
            float4 a = *(const float4*)(Asr + r * 128 + k);
            acc[r][0] += a.x * w0.x + a.y * w1.x + a.z * w2.x + a.w * w3.x;
            acc[r][1] += a.x * w0.y + a.y * w1.y + a.z * w2.y + a.w * w3.y;
            acc[r][2] += a.x * w0.z + a.y * w1.z + a.z * w2.z + a.w * w3.z;
            acc[r][3] += a.x * w0.w + a.y * w1.w + a.z * w2.w + a.w * w3.w;
        }
    }

    #pragma unroll
    for (int r = 0; r < 8; r++) {
        int row = row0 + ty * 8 + r;
        if (row < M)
            ((float4*)out)[(size_t)row * 32 + tx] =
                make_float4(acc[r][0], acc[r][1], acc[r][2], acc[r][3]);
    }
}

// ---------------- alpha: per-node per-head dot with a_src/a_dst ----------------
// one warp per node; lane owns 4 consecutive channels (all within one head since C>=4)
template <int H>
__global__ void alpha_kernel(const float* __restrict__ h,
                             const float* __restrict__ a_src,
                             const float* __restrict__ a_dst,
                             float* __restrict__ as_, float* __restrict__ ad_) {
    int warp = (blockIdx.x * blockDim.x + threadIdx.x) >> 5;
    int lane = threadIdx.x & 31;
    if (warp >= NNODES) return;
    float4 hv = ((const float4*)h)[(size_t)warp * 32 + lane];
    float4 s4 = ((const float4*)a_src)[lane];
    float4 d4 = ((const float4*)a_dst)[lane];
    float s = hv.x * s4.x + hv.y * s4.y + hv.z * s4.z + hv.w * s4.w;
    float d = hv.x * d4.x + hv.y * d4.y + hv.z * d4.z + hv.w * d4.w;
    const int G = 32 / H; // lanes per head (power of 2, aligned groups)
    #pragma unroll
    for (int off = G / 2; off > 0; off >>= 1) {
        s += __shfl_xor_sync(0xffffffffu, s, off);
        d += __shfl_xor_sync(0xffffffffu, d, off);
    }
    if ((lane & (G - 1)) == 0) {
        int hd = lane / G;
        as_[warp * H + hd] = s;
        ad_[warp * H + hd] = d;
    }
}

// ---------------- init: m=-inf, den=0, agg[n][j]=bias[j] ----------------
template <int H>
__global__ void init_kernel(float* __restrict__ m, float* __restrict__ den,
                            float* __restrict__ agg, const float* __restrict__ bias) {
    int idx = blockIdx.x * blockDim.x + threadIdx.x;
    if (idx >= NNODES * FDIM) return;
    agg[idx] = bias[idx & 127];
    if (idx < NNODES * H) {
        m[idx]   = __int_as_float(0xff800000); // -inf
        den[idx] = 0.f;
    }
}

// ---------------- edge pass 1: segment max of leaky_relu(as[src]+ad[dst]) ----------------
template <int H>
__global__ void edge_max_kernel(const int* __restrict__ src, const int* __restrict__ dst,
                                const float* __restrict__ as_, const float* __restrict__ ad_,
                                float* __restrict__ m) {
    int e = blockIdx.x * blockDim.x + threadIdx.x;
    if (e >= ETOT) return;
    int s, d;
    if (e < NEDGES) { s = src[e]; d = dst[e]; } else { s = d = e - NEDGES; }
    #pragma unroll
    for (int h = 0; h < H; h++) {
        float v = as_[s * H + h] + ad_[d * H + h];
        v = v >= 0.f ? v : 0.2f * v;
        atomicMaxF(&m[d * H + h], v);
    }
}

// ---------------- edge pass 2: ee = exp(e - m[dst]); den += ee ----------------
template <int H>
__global__ void edge_expsum_kernel(const int* __restrict__ src, const int* __restrict__ dst,
                                   const float* __restrict__ as_, const float* __restrict__ ad_,
                                   const float* __restrict__ m,
                                   float* __restrict__ ee, float* __restrict__ den) {
    int e = blockIdx.x * blockDim.x + threadIdx.x;
    if (e >= ETOT) return;
    int s, d;
    if (e < NEDGES) { s = src[e]; d = dst[e]; } else { s = d = e - NEDGES; }
    #pragma unroll
    for (int h = 0; h < H; h++) {
        float v = as_[s * H + h] + ad_[d * H + h];
        v = v >= 0.f ? v : 0.2f * v;
        float ev = __expf(v - m[d * H + h]);
        ee[(size_t)e * H + h] = ev;
        atomicAdd(&den[d * H + h], ev);
    }
}

// ---------------- edge pass 3: out[dst] += h[src] * w ----------------
// one warp per edge; lane owns 4 consecutive channels (float4 gather + 4 REDs)
template <int H>
__global__ void edge_agg_kernel(const int* __restrict__ src, const int* __restrict__ dst,
                                const float* __restrict__ ee, const float* __restrict__ den,
                                const float* __restrict__ h, float* __restrict__ out) {
    int gw   = (blockIdx.x * blockDim.x + threadIdx.x) >> 5;
    int lane = threadIdx.x & 31;
    if (gw >= ETOT) return;
    int s, d;
    if (gw < NEDGES) { s = src[gw]; d = dst[gw]; } else { s = d = gw - NEDGES; }
    float wv = 0.f;
    if (lane < H) wv = ee[(size_t)gw * H + lane] / (den[d * H + lane] + 1e-16f);
    const int C = 128 / H;
    int head = (lane * 4) / C;
    float myw = __shfl_sync(0xffffffffu, wv, head);
    float4 hv = ((const float4*)h)[(size_t)s * 32 + lane];
    float* o = out + (size_t)d * 128 + lane * 4;
    atomicAdd(o + 0, hv.x * myw);
    atomicAdd(o + 1, hv.y * myw);
    atomicAdd(o + 2, hv.z * myw);
    atomicAdd(o + 3, hv.w * myw);
}

// ---------------- ELU epilogue (layer 1) ----------------
__global__ void elu_kernel(const float* __restrict__ in, float* __restrict__ outp) {
    int idx = blockIdx.x * blockDim.x + threadIdx.x;
    if (idx >= NNODES * FDIM) return;
    float v = in[idx];
    outp[idx] = v > 0.f ? v : expm1f(v);
}

// ---------------- launch ----------------
extern "C" void kernel_launch(void* const* d_in, const int* in_sizes, int n_in,
                              void* d_out, int out_size) {
    const float* x      = (const float*)d_in[0];
    const int*   ei     = (const int*)d_in[1];
    const float* W1     = (const float*)d_in[2];
    const float* a_src1 = (const float*)d_in[3];
    const float* a_dst1 = (const float*)d_in[4];
    const float* b1     = (const float*)d_in[5];
    const float* W2     = (const float*)d_in[6];
    const float* a_src2 = (const float*)d_in[7];
    const float* a_dst2 = (const float*)d_in[8];
    const float* b2     = (const float*)d_in[9];
    float* out = (float*)d_out;

    const int* src = ei;
    const int* dst = ei + NEDGES;

    float *p_h, *p_feat, *p_agg, *p_as, *p_ad, *p_m, *p_den, *p_ee;
    cudaGetSymbolAddress((void**)&p_h,    g_h);
    cudaGetSymbolAddress((void**)&p_feat, g_feat);
    cudaGetSymbolAddress((void**)&p_agg,  g_agg);
    cudaGetSymbolAddress((void**)&p_as,   g_as);
    cudaGetSymbolAddress((void**)&p_ad,   g_ad);
    cudaGetSymbolAddress((void**)&p_m,    g_m);
    cudaGetSymbolAddress((void**)&p_den,  g_den);
    cudaGetSymbolAddress((void**)&p_ee,   g_ee);

    const int NT = 256;
    int gemm_blocks  = (NNODES + 63) / 64;
    int node_warps   = (NNODES * 32 + NT - 1) / NT;
    int nf_blocks    = (NNODES * FDIM + NT - 1) / NT;
    int edge_blocks  = (ETOT + NT - 1) / NT;
    int eagg_blocks  = ((size_t)ETOT * 32 + NT - 1) / NT;

    // ===== Layer 1 (H=4, C=32) =====
    gemm128_kernel<<<gemm_blocks, NT>>>(x, W1, p_h, NNODES);
    alpha_kernel<4><<<node_warps, NT>>>(p_h, a_src1, a_dst1, p_as, p_ad);
    init_kernel<4><<<nf_blocks, NT>>>(p_m, p_den, p_agg, b1);
    edge_max_kernel<4><<<edge_blocks, NT>>>(src, dst, p_as, p_ad, p_m);
    edge_expsum_kernel<4><<<edge_blocks, NT>>>(src, dst, p_as, p_ad, p_m, p_ee, p_den);
    edge_agg_kernel<4><<<eagg_blocks, NT>>>(src, dst, p_ee, p_den, p_h, p_agg);
    elu_kernel<<<nf_blocks, NT>>>(p_agg, p_feat);

    // ===== Layer 2 (H=1, C=128) =====
    gemm128_kernel<<<gemm_blocks, NT>>>(p_feat, W2, p_h, NNODES);
    alpha_kernel<1><<<node_warps, NT>>>(p_h, a_src2, a_dst2, p_as, p_ad);
    init_kernel<1><<<nf_blocks, NT>>>(p_m, p_den, out, b2);
    edge_max_kernel<1><<<edge_blocks, NT>>>(src, dst, p_as, p_ad, p_m);
    edge_expsum_kernel<1><<<edge_blocks, NT>>>(src, dst, p_as, p_ad, p_m, p_ee, p_den);
    edge_agg_kernel<1><<<eagg_blocks, NT>>>(src, dst, p_ee, p_den, p_h, out);
}

// round 2
// speedup vs baseline: 3.2589x; 3.2589x over previous
#include <cuda_runtime.h>
#include <math.h>

#define NNODES 100000
#define NEDGES 1600000
#define FDIM   128

// ---------------- scratch (static device allocations) ----------------
__device__ float g_h[NNODES * FDIM];     // GEMM output (per layer)
__device__ float g_feat[NNODES * FDIM];  // layer-1 activations (input to layer 2)
__device__ float g_as[NNODES * 4];       // alpha_src per node/head
__device__ float g_ad[NNODES * 4];       // alpha_dst per node/head
__device__ int   g_cnt[NNODES];          // degree counts (in-edges, no self loop)
__device__ int   g_rp[NNODES + 1];       // CSR row pointers (by dst)
__device__ int   g_cursor[NNODES];       // scatter cursors
__device__ int   g_bsum[64];             // scan block sums
__device__ int   g_csr[NEDGES];          // CSR column (src) indices

// ---------------- GEMM: out[M,128] = A[M,128] @ W[128,128] ----------------
__global__ void gemm128_kernel(const float* __restrict__ A,
                               const float* __restrict__ W,
                               float* __restrict__ out, int M) {
    __shared__ float As[64 * 128];
    int tid  = threadIdx.x;
    int row0 = blockIdx.x * 64;

    #pragma unroll
    for (int i = 0; i < 8; i++) {
        int idx = tid + 256 * i;
        int r   = idx >> 5;
        float4 v = make_float4(0.f, 0.f, 0.f, 0.f);
        if (row0 + r < M) v = ((const float4*)A)[(size_t)row0 * 32 + idx];
        ((float4*)As)[idx] = v;
    }
    __syncthreads();

    int tx = tid & 31;
    int ty = tid >> 5;
    const float* Asr = As + ty * 8 * 128;

    float acc[8][4];
    #pragma unroll
    for (int r = 0; r < 8; r++)
        #pragma unroll
        for (int c = 0; c < 4; c++) acc[r][c] = 0.f;

    for (int k = 0; k < 128; k += 4) {
        float4 w0 = __ldg(&((const float4*)(W + (k + 0) * 128))[tx]);
        float4 w1 = __ldg(&((const float4*)(W + (k + 1) * 128))[tx]);
        float4 w2 = __ldg(&((const float4*)(W + (k + 2) * 128))[tx]);
        float4 w3 = __ldg(&((const float4*)(W + (k + 3) * 128))[tx]);
        #pragma unroll
        for (int r = 0; r < 8; r++) {
            float4 a = *(const float4*)(Asr + r * 128 + k);
            acc[r][0] += a.x * w0.x + a.y * w1.x + a.z * w2.x + a.w * w3.x;
            acc[r][1] += a.x * w0.y + a.y * w1.y + a.z * w2.y + a.w * w3.y;
            acc[r][2] += a.x * w0.z + a.y * w1.z + a.z * w2.z + a.w * w3.z;
            acc[r][3] += a.x * w0.w + a.y * w1.w + a.z * w2.w + a.w * w3.w;
        }
    }

    #pragma unroll
    for (int r = 0; r < 8; r++) {
        int row = row0 + ty * 8 + r;
        if (row < M)
            ((float4*)out)[(size_t)row * 32 + tx] =
                make_float4(acc[r][0], acc[r][1], acc[r][2], acc[r][3]);
    }
}

// ---------------- alpha: per-node per-head dot with a_src/a_dst ----------------
template <int H>
__global__ void alpha_kernel(const float* __restrict__ h,
                             const float* __restrict__ a_src,
                             const float* __restrict__ a_dst,
                             float* __restrict__ as_, float* __restrict__ ad_) {
    int warp = (blockIdx.x * blockDim.x + threadIdx.x) >> 5;
    int lane = threadIdx.x & 31;
    if (warp >= NNODES) return;
    float4 hv = ((const float4*)h)[(size_t)warp * 32 + lane];
    float4 s4 = ((const float4*)a_src)[lane];
    float4 d4 = ((const float4*)a_dst)[lane];
    float s = hv.x * s4.x + hv.y * s4.y + hv.z * s4.z + hv.w * s4.w;
    float d = hv.x * d4.x + hv.y * d4.y + hv.z * d4.z + hv.w * d4.w;
    const int G = 32 / H;
    #pragma unroll
    for (int off = G / 2; off > 0; off >>= 1) {
        s += __shfl_xor_sync(0xffffffffu, s, off);
        d += __shfl_xor_sync(0xffffffffu, d, off);
    }
    if ((lane & (G - 1)) == 0) {
        int hd = lane / G;
        as_[warp * H + hd] = s;
        ad_[warp * H + hd] = d;
    }
}

// ---------------- CSR construction ----------------
__global__ void zero_cnt_kernel(int* __restrict__ cnt) {
    int i = blockIdx.x * blockDim.x + threadIdx.x;
    if (i < NNODES) cnt[i] = 0;
}

__global__ void count_kernel(const int* __restrict__ dst, int* __restrict__ cnt) {
    int e = blockIdx.x * blockDim.x + threadIdx.x;
    if (e < NEDGES) atomicAdd(&cnt[dst[e]], 1);
}

// block-local exclusive scan: 512 threads x 8 elems = 4096/block
__global__ void scan_local_kernel(const int* __restrict__ cnt,
                                  int* __restrict__ excl, int* __restrict__ bsum) {
    __shared__ int sh[512];
    int t = threadIdx.x;
    int base = blockIdx.x * 4096 + t * 8;
    int v[8];
    int run = 0;
    #pragma unroll
    for (int j = 0; j < 8; j++) {
        int c = (base + j < NNODES) ? cnt[base + j] : 0;
        v[j] = run;
        run += c;
    }
    sh[t] = run;
    __syncthreads();
    for (int off = 1; off < 512; off <<= 1) {
        int x = (t >= off) ? sh[t - off] : 0;
        __syncthreads();
        sh[t] += x;
        __syncthreads();
    }
    int excl_t = sh[t] - run;
    if (t == 511) bsum[blockIdx.x] = sh[511];
    #pragma unroll
    for (int j = 0; j < 8; j++)
        if (base + j < NNODES) excl[base + j] = excl_t + v[j];
}

__global__ void scan_top_kernel(int* __restrict__ bsum, int nb) {
    if (threadIdx.x == 0 && blockIdx.x == 0) {
        int run = 0;
        for (int i = 0; i < nb; i++) { int c = bsum[i]; bsum[i] = run; run += c; }
    }
}

__global__ void scan_add_kernel(const int* __restrict__ excl, const int* __restrict__ bsum,
                                int* __restrict__ rp, int* __restrict__ cursor) {
    int i = blockIdx.x * blockDim.x + threadIdx.x;
    if (i < NNODES) {
        int v = excl[i] + bsum[i >> 12];
        rp[i] = v;
        cursor[i] = v;
    }
    if (i == NNODES) rp[NNODES] = NEDGES;
}

__global__ void scatter_kernel(const int* __restrict__ src, const int* __restrict__ dst,
                               int* __restrict__ cursor, int* __restrict__ csr) {
    int e = blockIdx.x * blockDim.x + threadIdx.x;
    if (e >= NEDGES) return;
    int p = atomicAdd(&cursor[dst[e]], 1);
    csr[p] = src[e];
}

// ---------------- fused softmax + aggregation: one warp per dst node ----------------
// Includes the implicit self loop. Epilogue: + bias, optional ELU.
template <int H, bool ELU>
__global__ void fused_agg_kernel(const int* __restrict__ rp, const int* __restrict__ csr,
                                 const float* __restrict__ as_, const float* __restrict__ ad_,
                                 const float* __restrict__ hfeat,
                                 const float* __restrict__ bias,
                                 float* __restrict__ outp) {
    int d    = (blockIdx.x * blockDim.x + threadIdx.x) >> 5;
    int lane = threadIdx.x & 31;
    if (d >= NNODES) return;
    int beg = rp[d], end = rp[d + 1];

    float adv[H], selfe[H];
    #pragma unroll
    for (int h = 0; h < H; h++) {
        adv[h] = ad_[d * H + h];
        float v = as_[d * H + h] + adv[h];
        selfe[h] = v >= 0.f ? v : 0.2f * v;
    }

    // pass 1: segment max (edge-parallel across lanes)
    float mx[H];
    #pragma unroll
    for (int h = 0; h < H; h++) mx[h] = selfe[h];
    for (int i = beg + lane; i < end; i += 32) {
        int s = csr[i];
        float a[H];
        if (H == 4) { float4 t = ((const float4*)as_)[s]; a[0] = t.x; a[1] = t.y; a[2] = t.z; a[3] = t.w; }
        else        { a[0] = as_[s]; }
        #pragma unroll
        for (int h = 0; h < H; h++) {
            float v = a[h] + adv[h];
            v = v >= 0.f ? v : 0.2f * v;
            mx[h] = fmaxf(mx[h], v);
        }
    }
    #pragma unroll
    for (int h = 0; h < H; h++)
        #pragma unroll
        for (int off = 16; off > 0; off >>= 1)
            mx[h] = fmaxf(mx[h], __shfl_xor_sync(0xffffffffu, mx[h], off));

    // pass 2: denominator (edge-parallel across lanes)
    float den[H];
    #pragma unroll
    for (int h = 0; h < H; h++) den[h] = 0.f;
    for (int i = beg + lane; i < end; i += 32) {
        int s = csr[i];
        float a[H];
        if (H == 4) { float4 t = ((const float4*)as_)[s]; a[0] = t.x; a[1] = t.y; a[2] = t.z; a[3] = t.w; }
        else        { a[0] = as_[s]; }
        #pragma unroll
        for (int h = 0; h < H; h++) {
            float v = a[h] + adv[h];
            v = v >= 0.f ? v : 0.2f * v;
            den[h] += __expf(v - mx[h]);
        }
    }
    #pragma unroll
    for (int h = 0; h < H; h++) {
        #pragma unroll
        for (int off = 16; off > 0; off >>= 1)
            den[h] += __shfl_xor_sync(0xffffffffu, den[h], off);
        den[h] += __expf(selfe[h] - mx[h]);  // self loop
    }
    float inv[H];
    #pragma unroll
    for (int h = 0; h < H; h++) inv[h] = 1.f / (den[h] + 1e-16f);

    // pass 3: channel-parallel accumulation (lane owns 4 consecutive channels)
    const int C = 128 / H;
    const int myh = (lane * 4) / C;
    float adm = adv[myh], mxm = mx[myh], invm = inv[myh];

    float wself = __expf(selfe[myh] - mxm) * invm;
    float4 hv = ((const float4*)hfeat)[(size_t)d * 32 + lane];
    float4 acc = make_float4(hv.x * wself, hv.y * wself, hv.z * wself, hv.w * wself);

    int i = beg;
    for (; i + 1 < end; i += 2) {
        int s0 = csr[i], s1 = csr[i + 1];
        float v0 = as_[s0 * H + myh] + adm;
        float v1 = as_[s1 * H + myh] + adm;
        v0 = v0 >= 0.f ? v0 : 0.2f * v0;
        v1 = v1 >= 0.f ? v1 : 0.2f * v1;
        float w0 = __expf(v0 - mxm) * invm;
        float w1 = __expf(v1 - mxm) * invm;
        float4 g0 = ((const float4*)hfeat)[(size_t)s0 * 32 + lane];
        float4 g1 = ((const float4*)hfeat)[(size_t)s1 * 32 + lane];
        acc.x += g0.x * w0 + g1.x * w1;
        acc.y += g0.y * w0 + g1.y * w1;
        acc.z += g0.z * w0 + g1.z * w1;
        acc.w += g0.w * w0 + g1.w * w1;
    }
    if (i < end) {
        int s0 = csr[i];
        float v0 = as_[s0 * H + myh] + adm;
        v0 = v0 >= 0.f ? v0 : 0.2f * v0;
        float w0 = __expf(v0 - mxm) * invm;
        float4 g0 = ((const float4*)hfeat)[(size_t)s0 * 32 + lane];
        acc.x += g0.x * w0;
        acc.y += g0.y * w0;
        acc.z += g0.z * w0;
        acc.w += g0.w * w0;
    }

    float4 b = ((const float4*)bias)[lane];
    acc.x += b.x; acc.y += b.y; acc.z += b.z; acc.w += b.w;
    if (ELU) {
        acc.x = acc.x > 0.f ? acc.x : expm1f(acc.x);
        acc.y = acc.y > 0.f ? acc.y : expm1f(acc.y);
        acc.z = acc.z > 0.f ? acc.z : expm1f(acc.z);
        acc.w = acc.w > 0.f ? acc.w : expm1f(acc.w);
    }
    ((float4*)outp)[(size_t)d * 32 + lane] = acc;
}

// ---------------- launch ----------------
extern "C" void kernel_launch(void* const* d_in, const int* in_sizes, int n_in,
                              void* d_out, int out_size) {
    const float* x      = (const float*)d_in[0];
    const int*   ei     = (const int*)d_in[1];
    const float* W1     = (const float*)d_in[2];
    const float* a_src1 = (const float*)d_in[3];
    const float* a_dst1 = (const float*)d_in[4];
    const float* b1     = (const float*)d_in[5];
    const float* W2     = (const float*)d_in[6];
    const float* a_src2 = (const float*)d_in[7];
    const float* a_dst2 = (const float*)d_in[8];
    const float* b2     = (const float*)d_in[9];
    float* out = (float*)d_out;

    const int* src = ei;
    const int* dst = ei + NEDGES;

    float *p_h, *p_feat, *p_as, *p_ad;
    int *p_cnt, *p_rp, *p_cursor, *p_bsum, *p_csr;
    cudaGetSymbolAddress((void**)&p_h,      g_h);
    cudaGetSymbolAddress((void**)&p_feat,   g_feat);
    cudaGetSymbolAddress((void**)&p_as,     g_as);
    cudaGetSymbolAddress((void**)&p_ad,     g_ad);
    cudaGetSymbolAddress((void**)&p_cnt,    g_cnt);
    cudaGetSymbolAddress((void**)&p_rp,     g_rp);
    cudaGetSymbolAddress((void**)&p_cursor, g_cursor);
    cudaGetSymbolAddress((void**)&p_bsum,   g_bsum);
    cudaGetSymbolAddress((void**)&p_csr,    g_csr);

    const int NT = 256;
    int gemm_blocks = (NNODES + 63) / 64;
    int node_warps  = (NNODES * 32 + NT - 1) / NT;
    int node_blocks = (NNODES + NT - 1) / NT;
    int node1_blocks = (NNODES + 1 + NT - 1) / NT;
    int edge_blocks = (NEDGES + NT - 1) / NT;
    int scan_blocks = (NNODES + 4095) / 4096;  // 25

    // ===== CSR build (shared by both layers) =====
    zero_cnt_kernel<<<node_blocks, NT>>>(p_cnt);
    count_kernel<<<edge_blocks, NT>>>(dst, p_cnt);
    scan_local_kernel<<<scan_blocks, 512>>>(p_cnt, p_cnt, p_bsum);  // in-place ok (elementwise)
    scan_top_kernel<<<1, 32>>>(p_bsum, scan_blocks);
    scan_add_kernel<<<node1_blocks, NT>>>(p_cnt, p_bsum, p_rp, p_cursor);
    scatter_kernel<<<edge_blocks, NT>>>(src, dst, p_cursor, p_csr);

    // ===== Layer 1 (H=4, C=32) =====
    gemm128_kernel<<<gemm_blocks, NT>>>(x, W1, p_h, NNODES);
    alpha_kernel<4><<<node_warps, NT>>>(p_h, a_src1, a_dst1, p_as, p_ad);
    fused_agg_kernel<4, true><<<node_warps, NT>>>(p_rp, p_csr, p_as, p_ad, p_h, b1, p_feat);

    // ===== Layer 2 (H=1, C=128) =====
    gemm128_kernel<<<gemm_blocks, NT>>>(p_feat, W2, p_h, NNODES);
    alpha_kernel<1><<<node_warps, NT>>>(p_h, a_src2, a_dst2, p_as, p_ad);
    fused_agg_kernel<1, false><<<node_warps, NT>>>(p_rp, p_csr, p_as, p_ad, p_h, b2, out);
}

// round 3
// speedup vs baseline: 3.9976x; 1.2267x over previous
#include <cuda_runtime.h>
#include <math.h>

#define NNODES 100000
#define NEDGES 1600000
#define FDIM   128

// ---------------- scratch ----------------
__device__ float g_h[NNODES * FDIM];
__device__ float g_feat[NNODES * FDIM];
__device__ float g_as[NNODES * 4];
__device__ float g_ad[NNODES * 4];
__device__ int   g_cnt[NNODES];
__device__ int   g_rp[NNODES + 1];
__device__ int   g_cursor[NNODES];
__device__ int   g_bsum[64];
__device__ int   g_csr[NEDGES];

// ---------------- f32x2 helpers (sm_103a packed fp32) ----------------
__device__ __forceinline__ unsigned long long pack2(float x) {
    unsigned long long r;
    asm("mov.b64 %0, {%1, %1};" : "=l"(r) : "r"(__float_as_uint(x)));
    return r;
}
#define FMA2(d, a, b) asm("fma.rn.f32x2 %0, %1, %2, %0;" : "+l"(d) : "l"(a), "l"(b))
__device__ __forceinline__ void unpack2(unsigned long long p, float& lo, float& hi) {
    asm("mov.b64 {%0, %1}, %2;" : "=f"(lo), "=f"(hi) : "l"(p));
}

// ---------------- GEMM + fused alpha epilogue ----------------
// out[M,128] = A[M,128] @ W[128,128]; also as_[n,H] = <out_row, a_src>, ad_ likewise.
// 64 rows/block, 256 threads. A tile transposed in shared: As[k][row] (pad 66).
// Each thread: 4 row-pairs (packed f32x2) x 4 cols.
template <int H>
__global__ void gemm_alpha_kernel(const float* __restrict__ A,
                                  const float* __restrict__ W,
                                  float* __restrict__ out, int M,
                                  const float* __restrict__ a_src,
                                  const float* __restrict__ a_dst,
                                  float* __restrict__ as_, float* __restrict__ ad_) {
    __shared__ float As[128 * 66];
    int tid  = threadIdx.x;
    int row0 = blockIdx.x * 64;
    int tx = tid & 31;   // col group: cols tx*4..tx*4+3
    int ty = tid >> 5;   // row group: rows ty*8..ty*8+7

    // load + transpose A tile
    #pragma unroll
    for (int i = 0; i < 8; i++) {
        int idx = tid + 256 * i;      // float4 index
        int r   = idx >> 5;
        int c4  = idx & 31;
        float4 v = make_float4(0.f, 0.f, 0.f, 0.f);
        if (row0 + r < M) v = ((const float4*)A)[(size_t)(row0 + r) * 32 + c4];
        int c = c4 * 4;
        As[(c + 0) * 66 + r] = v.x;
        As[(c + 1) * 66 + r] = v.y;
        As[(c + 2) * 66 + r] = v.z;
        As[(c + 3) * 66 + r] = v.w;
    }
    __syncthreads();

    unsigned long long acc[4][4];   // [rowpair][col]
    #pragma unroll
    for (int p = 0; p < 4; p++)
        #pragma unroll
        for (int c = 0; c < 4; c++) acc[p][c] = 0ull;

    const float* asbase = As + ty * 8;
    #pragma unroll 4
    for (int k = 0; k < 128; k++) {
        float4 w = __ldg(&((const float4*)(W + k * 128))[tx]);
        unsigned long long w0 = pack2(w.x), w1 = pack2(w.y),
                           w2 = pack2(w.z), w3 = pack2(w.w);
        const unsigned long long* ap =
            (const unsigned long long*)(asbase + k * 66);
        unsigned long long a0 = ap[0], a1 = ap[1], a2 = ap[2], a3 = ap[3];
        FMA2(acc[0][0], a0, w0); FMA2(acc[0][1], a0, w1);
        FMA2(acc[0][2], a0, w2); FMA2(acc[0][3], a0, w3);
        FMA2(acc[1][0], a1, w0); FMA2(acc[1][1], a1, w1);
        FMA2(acc[1][2], a1, w2); FMA2(acc[1][3], a1, w3);
        FMA2(acc[2][0], a2, w0); FMA2(acc[2][1], a2, w1);
        FMA2(acc[2][2], a2, w2); FMA2(acc[2][3], a2, w3);
        FMA2(acc[3][0], a3, w0); FMA2(acc[3][1], a3, w1);
        FMA2(acc[3][2], a3, w2); FMA2(acc[3][3], a3, w3);
    }

    // epilogue: unpack, write, fused alpha dots
    float4 s4 = ((const float4*)a_src)[tx];
    float4 d4 = ((const float4*)a_dst)[tx];
    const int G = 32 / H;   // lanes per head

    #pragma unroll
    for (int p = 0; p < 4; p++) {
        float lo[4], hi[4];
        #pragma unroll
        for (int c = 0; c < 4; c++) unpack2(acc[p][c], lo[c], hi[c]);

        #pragma unroll
        for (int half = 0; half < 2; half++) {
            float* v = half ? hi : lo;
            int row = row0 + ty * 8 + p * 2 + half;
            bool ok = row < M;
            if (ok)
                ((float4*)out)[(size_t)row * 32 + tx] =
                    make_float4(v[0], v[1], v[2], v[3]);
            float s = v[0] * s4.x + v[1] * s4.y + v[2] * s4.z + v[3] * s4.w;
            float d = v[0] * d4.x + v[1] * d4.y + v[2] * d4.z + v[3] * d4.w;
            #pragma unroll
            for (int off = G / 2; off > 0; off >>= 1) {
                s += __shfl_xor_sync(0xffffffffu, s, off);
                d += __shfl_xor_sync(0xffffffffu, d, off);
            }
            if (ok && (tx & (G - 1)) == 0) {
                int hd = tx / G;
                as_[row * H + hd] = s;
                ad_[row * H + hd] = d;
            }
        }
    }
}

// ---------------- CSR construction ----------------
__global__ void zero_cnt_kernel(int* __restrict__ cnt) {
    int i = blockIdx.x * blockDim.x + threadIdx.x;
    if (i < NNODES) cnt[i] = 0;
}

__global__ void count_kernel(const int* __restrict__ dst, int* __restrict__ cnt) {
    int e = blockIdx.x * blockDim.x + threadIdx.x;
    if (e < NEDGES) atomicAdd(&cnt[dst[e]], 1);
}

__global__ void scan_local_kernel(const int* __restrict__ cnt,
                                  int* __restrict__ excl, int* __restrict__ bsum) {
    __shared__ int sh[512];
    int t = threadIdx.x;
    int base = blockIdx.x * 4096 + t * 8;
    int v[8];
    int run = 0;
    #pragma unroll
    for (int j = 0; j < 8; j++) {
        int c = (base + j < NNODES) ? cnt[base + j] : 0;
        v[j] = run;
        run += c;
    }
    sh[t] = run;
    __syncthreads();
    for (int off = 1; off < 512; off <<= 1) {
        int x = (t >= off) ? sh[t - off] : 0;
        __syncthreads();
        sh[t] += x;
        __syncthreads();
    }
    int excl_t = sh[t] - run;
    if (t == 511) bsum[blockIdx.x] = sh[511];
    #pragma unroll
    for (int j = 0; j < 8; j++)
        if (base + j < NNODES) excl[base + j] = excl_t + v[j];
}

__global__ void scan_top_kernel(int* __restrict__ bsum, int nb) {
    if (threadIdx.x == 0 && blockIdx.x == 0) {
        int run = 0;
        for (int i = 0; i < nb; i++) { int c = bsum[i]; bsum[i] = run; run += c; }
    }
}

__global__ void scan_add_kernel(const int* __restrict__ excl, const int* __restrict__ bsum,
                                int* __restrict__ rp, int* __restrict__ cursor) {
    int i = blockIdx.x * blockDim.x + threadIdx.x;
    if (i < NNODES) {
        int v = excl[i] + bsum[i >> 12];
        rp[i] = v;
        cursor[i] = v;
    }
    if (i == NNODES) rp[NNODES] = NEDGES;
}

__global__ void scatter_kernel(const int* __restrict__ src, const int* __restrict__ dst,
                               int* __restrict__ cursor, int* __restrict__ csr) {
    int e = blockIdx.x * blockDim.x + threadIdx.x;
    if (e >= NEDGES) return;
    int p = atomicAdd(&cursor[dst[e]], 1);
    csr[p] = src[e];
}

// ---------------- fused aggregation: single pass, one warp per dst node ----------------
// Softmax is max-shift-free (ratio invariant; logits are O(1), no overflow).
// Each lane visits every edge and owns 4 channels; den accumulated redundantly per lane.
template <int H, bool ELU>
__global__ void fused_agg_kernel(const int* __restrict__ rowp, const int* __restrict__ csr,
                                 const float* __restrict__ as_, const float* __restrict__ ad_,
                                 const float* __restrict__ hfeat,
                                 const float* __restrict__ bias,
                                 float* __restrict__ outp) {
    int d    = (blockIdx.x * blockDim.x + threadIdx.x) >> 5;
    int lane = threadIdx.x & 31;
    if (d >= NNODES) return;
    int beg = rowp[d], end = rowp[d + 1];

    const int G = 32 / H;
    const int myh = lane / G;
    float adm = ad_[d * H + myh];

    // self loop
    float sv = as_[d * H + myh] + adm;
    sv = sv >= 0.f ? sv : 0.2f * sv;
    float ev = __expf(sv);
    float den = ev;
    float4 hv = ((const float4*)hfeat)[(size_t)d * 32 + lane];
    float4 acc = make_float4(hv.x * ev, hv.y * ev, hv.z * ev, hv.w * ev);

    int i = beg;
    for (; i + 1 < end; i += 2) {
        int s0 = csr[i], s1 = csr[i + 1];
        float v0 = as_[s0 * H + myh] + adm;
        float v1 = as_[s1 * H + myh] + adm;
        v0 = v0 >= 0.f ? v0 : 0.2f * v0;
        v1 = v1 >= 0.f ? v1 : 0.2f * v1;
        float e0 = __expf(v0);
        float e1 = __expf(v1);
        float4 g0 = ((const float4*)hfeat)[(size_t)s0 * 32 + lane];
        float4 g1 = ((const float4*)hfeat)[(size_t)s1 * 32 + lane];
        den += e0 + e1;
        acc.x += g0.x * e0 + g1.x * e1;
        acc.y += g0.y * e0 + g1.y * e1;
        acc.z += g0.z * e0 + g1.z * e1;
        acc.w += g0.w * e0 + g1.w * e1;
    }
    if (i < end) {
        int s0 = csr[i];
        float v0 = as_[s0 * H + myh] + adm;
        v0 = v0 >= 0.f ? v0 : 0.2f * v0;
        float e0 = __expf(v0);
        float4 g0 = ((const float4*)hfeat)[(size_t)s0 * 32 + lane];
        den += e0;
        acc.x += g0.x * e0;
        acc.y += g0.y * e0;
        acc.z += g0.z * e0;
        acc.w += g0.w * e0;
    }

    float inv = 1.f / (den + 1e-16f);
    float4 b = ((const float4*)bias)[lane];
    acc.x = acc.x * inv + b.x;
    acc.y = acc.y * inv + b.y;
    acc.z = acc.z * inv + b.z;
    acc.w = acc.w * inv + b.w;
    if (ELU) {
        acc.x = acc.x > 0.f ? acc.x : expm1f(acc.x);
        acc.y = acc.y > 0.f ? acc.y : expm1f(acc.y);
        acc.z = acc.z > 0.f ? acc.z : expm1f(acc.z);
        acc.w = acc.w > 0.f ? acc.w : expm1f(acc.w);
    }
    ((float4*)outp)[(size_t)d * 32 + lane] = acc;
}

// ---------------- launch ----------------
extern "C" void kernel_launch(void* const* d_in, const int* in_sizes, int n_in,
                              void* d_out, int out_size) {
    const float* x      = (const float*)d_in[0];
    const int*   ei     = (const int*)d_in[1];
    const float* W1     = (const float*)d_in[2];
    const float* a_src1 = (const float*)d_in[3];
    const float* a_dst1 = (const float*)d_in[4];
    const float* b1     = (const float*)d_in[5];
    const float* W2     = (const float*)d_in[6];
    const float* a_src2 = (const float*)d_in[7];
    const float* a_dst2 = (const float*)d_in[8];
    const float* b2     = (const float*)d_in[9];
    float* out = (float*)d_out;

    const int* src = ei;
    const int* dst = ei + NEDGES;

    float *p_h, *p_feat, *p_as, *p_ad;
    int *p_cnt, *p_rp, *p_cursor, *p_bsum, *p_csr;
    cudaGetSymbolAddress((void**)&p_h,      g_h);
    cudaGetSymbolAddress((void**)&p_feat,   g_feat);
    cudaGetSymbolAddress((void**)&p_as,     g_as);
    cudaGetSymbolAddress((void**)&p_ad,     g_ad);
    cudaGetSymbolAddress((void**)&p_cnt,    g_cnt);
    cudaGetSymbolAddress((void**)&p_rp,     g_rp);
    cudaGetSymbolAddress((void**)&p_cursor, g_cursor);
    cudaGetSymbolAddress((void**)&p_bsum,   g_bsum);
    cudaGetSymbolAddress((void**)&p_csr,    g_csr);

    const int NT = 256;
    int gemm_blocks  = (NNODES + 63) / 64;
    int node_warps   = (NNODES * 32 + NT - 1) / NT;
    int node_blocks  = (NNODES + NT - 1) / NT;
    int node1_blocks = (NNODES + 1 + NT - 1) / NT;
    int edge_blocks  = (NEDGES + NT - 1) / NT;
    int scan_blocks  = (NNODES + 4095) / 4096;

    // GEMM1 (+alpha) is independent of CSR build — launch first
    gemm_alpha_kernel<4><<<gemm_blocks, NT>>>(x, W1, p_h, NNODES,
                                              a_src1, a_dst1, p_as, p_ad);

    // CSR build (shared by both layers)
    zero_cnt_kernel<<<node_blocks, NT>>>(p_cnt);
    count_kernel<<<edge_blocks, NT>>>(dst, p_cnt);
    scan_local_kernel<<<scan_blocks, 512>>>(p_cnt, p_cnt, p_bsum);
    scan_top_kernel<<<1, 32>>>(p_bsum, scan_blocks);
    scan_add_kernel<<<node1_blocks, NT>>>(p_cnt, p_bsum, p_rp, p_cursor);
    scatter_kernel<<<edge_blocks, NT>>>(src, dst, p_cursor, p_csr);

    // Layer 1 aggregation (H=4) + ELU
    fused_agg_kernel<4, true><<<node_warps, NT>>>(p_rp, p_csr, p_as, p_ad, p_h, b1, p_feat);

    // Layer 2
    gemm_alpha_kernel<1><<<gemm_blocks, NT>>>(p_feat, W2, p_h, NNODES,
                                              a_src2, a_dst2, p_as, p_ad);
    fused_agg_kernel<1, false><<<node_warps, NT>>>(p_rp, p_csr, p_as, p_ad, p_h, b2, out);
}

// round 4
// speedup vs baseline: 4.0572x; 1.0149x over previous
#include <cuda_runtime.h>
#include <math.h>

#define NNODES 100000
#define NEDGES 1600000
#define FDIM   128

// ---------------- scratch ----------------
__device__ float g_h[NNODES * FDIM];
__device__ float g_feat[NNODES * FDIM];
__device__ float g_as[NNODES * 4];
__device__ float g_ad[NNODES * 4];
__device__ int   g_cnt[NNODES];
__device__ int   g_rp[NNODES + 1];
__device__ int   g_cursor[NNODES];
__device__ int   g_bsum[64];
__device__ int   g_csr[NEDGES];

// ---------------- f32x2 helpers (sm_103a packed fp32) ----------------
__device__ __forceinline__ unsigned long long pack2(float x) {
    unsigned long long r;
    asm("mov.b64 %0, {%1, %1};" : "=l"(r) : "r"(__float_as_uint(x)));
    return r;
}
#define FMA2(d, a, b) asm("fma.rn.f32x2 %0, %1, %2, %0;" : "+l"(d) : "l"(a), "l"(b))
__device__ __forceinline__ void unpack2(unsigned long long p, float& lo, float& hi) {
    asm("mov.b64 {%0, %1}, %2;" : "=f"(lo), "=f"(hi) : "l"(p));
}

// ---------------- GEMM + fused alpha epilogue ----------------
template <int H>
__global__ void gemm_alpha_kernel(const float* __restrict__ A,
                                  const float* __restrict__ W,
                                  float* __restrict__ out, int M,
                                  const float* __restrict__ a_src,
                                  const float* __restrict__ a_dst,
                                  float* __restrict__ as_, float* __restrict__ ad_) {
    __shared__ float As[128 * 66];
    int tid  = threadIdx.x;
    int row0 = blockIdx.x * 64;
    int tx = tid & 31;   // col group: cols tx*4..tx*4+3
    int ty = tid >> 5;   // row group: rows ty*8..ty*8+7

    // load + transpose A tile
    #pragma unroll
    for (int i = 0; i < 8; i++) {
        int idx = tid + 256 * i;      // float4 index
        int r   = idx >> 5;
        int c4  = idx & 31;
        float4 v = make_float4(0.f, 0.f, 0.f, 0.f);
        if (row0 + r < M) v = ((const float4*)A)[(size_t)(row0 + r) * 32 + c4];
        int c = c4 * 4;
        As[(c + 0) * 66 + r] = v.x;
        As[(c + 1) * 66 + r] = v.y;
        As[(c + 2) * 66 + r] = v.z;
        As[(c + 3) * 66 + r] = v.w;
    }
    __syncthreads();

    unsigned long long acc[4][4];   // [rowpair][col]
    #pragma unroll
    for (int p = 0; p < 4; p++)
        #pragma unroll
        for (int c = 0; c < 4; c++) acc[p][c] = 0ull;

    const float* asbase = As + ty * 8;
    #pragma unroll 4
    for (int k = 0; k < 128; k++) {
        float4 w = __ldg(&((const float4*)(W + k * 128))[tx]);
        unsigned long long w0 = pack2(w.x), w1 = pack2(w.y),
                           w2 = pack2(w.z), w3 = pack2(w.w);
        const unsigned long long* ap =
            (const unsigned long long*)(asbase + k * 66);
        unsigned long long a0 = ap[0], a1 = ap[1], a2 = ap[2], a3 = ap[3];
        FMA2(acc[0][0], a0, w0); FMA2(acc[0][1], a0, w1);
        FMA2(acc[0][2], a0, w2); FMA2(acc[0][3], a0, w3);
        FMA2(acc[1][0], a1, w0); FMA2(acc[1][1], a1, w1);
        FMA2(acc[1][2], a1, w2); FMA2(acc[1][3], a1, w3);
        FMA2(acc[2][0], a2, w0); FMA2(acc[2][1], a2, w1);
        FMA2(acc[2][2], a2, w2); FMA2(acc[2][3], a2, w3);
        FMA2(acc[3][0], a3, w0); FMA2(acc[3][1], a3, w1);
        FMA2(acc[3][2], a3, w2); FMA2(acc[3][3], a3, w3);
    }

    // epilogue: unpack, write, fused alpha dots
    float4 s4 = ((const float4*)a_src)[tx];
    float4 d4 = ((const float4*)a_dst)[tx];
    const int G = 32 / H;   // lanes per head

    #pragma unroll
    for (int p = 0; p < 4; p++) {
        float lo[4], hi[4];
        #pragma unroll
        for (int c = 0; c < 4; c++) unpack2(acc[p][c], lo[c], hi[c]);

        #pragma unroll
        for (int half = 0; half < 2; half++) {
            float* v = half ? hi : lo;
            int row = row0 + ty * 8 + p * 2 + half;
            bool ok = row < M;
            if (ok)
                ((float4*)out)[(size_t)row * 32 + tx] =
                    make_float4(v[0], v[1], v[2], v[3]);
            float s = v[0] * s4.x + v[1] * s4.y + v[2] * s4.z + v[3] * s4.w;
            float d = v[0] * d4.x + v[1] * d4.y + v[2] * d4.z + v[3] * d4.w;
            #pragma unroll
            for (int off = G / 2; off > 0; off >>= 1) {
                s += __shfl_xor_sync(0xffffffffu, s, off);
                d += __shfl_xor_sync(0xffffffffu, d, off);
            }
            if (ok && (tx & (G - 1)) == 0) {
                int hd = tx / G;
                as_[row * H + hd] = s;
                ad_[row * H + hd] = d;
            }
        }
    }
}

// ---------------- CSR construction ----------------
__global__ void count_kernel(const int* __restrict__ dst, int* __restrict__ cnt) {
    int e = blockIdx.x * blockDim.x + threadIdx.x;
    if (e < NEDGES) atomicAdd(&cnt[dst[e]], 1);
}

__global__ void scan_local_kernel(const int* __restrict__ cnt,
                                  int* __restrict__ excl, int* __restrict__ bsum) {
    __shared__ int sh[512];
    int t = threadIdx.x;
    int base = blockIdx.x * 4096 + t * 8;
    int v[8];
    int run = 0;
    #pragma unroll
    for (int j = 0; j < 8; j++) {
        int c = (base + j < NNODES) ? cnt[base + j] : 0;
        v[j] = run;
        run += c;
    }
    sh[t] = run;
    __syncthreads();
    for (int off = 1; off < 512; off <<= 1) {
        int x = (t >= off) ? sh[t - off] : 0;
        __syncthreads();
        sh[t] += x;
        __syncthreads();
    }
    int excl_t = sh[t] - run;
    if (t == 511) bsum[blockIdx.x] = sh[511];
    #pragma unroll
    for (int j = 0; j < 8; j++)
        if (base + j < NNODES) excl[base + j] = excl_t + v[j];
}

// scan_add with folded top-level scan over the (<=64) block sums
__global__ void scan_add_kernel(const int* __restrict__ excl, const int* __restrict__ bsum,
                                int* __restrict__ rp, int* __restrict__ cursor, int nb) {
    int i = blockIdx.x * blockDim.x + threadIdx.x;
    if (i <= NNODES) {
        int blk = i >> 12;
        int base = 0;
        for (int j = 0; j < nb; j++)
            if (j < blk) base += bsum[j];
        if (i < NNODES) {
            int v = excl[i] + base;
            rp[i] = v;
            cursor[i] = v;
        } else {
            rp[NNODES] = NEDGES;
        }
    }
}

__global__ void scatter_kernel(const int* __restrict__ src, const int* __restrict__ dst,
                               int* __restrict__ cursor, int* __restrict__ csr) {
    int e = blockIdx.x * blockDim.x + threadIdx.x;
    if (e >= NEDGES) return;
    int p = atomicAdd(&cursor[dst[e]], 1);
    csr[p] = src[e];
}

// ---------------- fused aggregation: single pass, one warp per dst node ----------------
template <int H, bool ELU>
__global__ void fused_agg_kernel(const int* __restrict__ rowp, const int* __restrict__ csr,
                                 const float* __restrict__ as_, const float* __restrict__ ad_,
                                 const float* __restrict__ hfeat,
                                 const float* __restrict__ bias,
                                 float* __restrict__ outp) {
    int d    = (blockIdx.x * blockDim.x + threadIdx.x) >> 5;
    int lane = threadIdx.x & 31;
    if (d >= NNODES) return;
    int beg = rowp[d], end = rowp[d + 1];

    const int G = 32 / H;
    const int myh = lane / G;
    float adm = ad_[d * H + myh];

    // self loop
    float sv = as_[d * H + myh] + adm;
    sv = sv >= 0.f ? sv : 0.2f * sv;
    float ev = __expf(sv);
    float den = ev;
    float4 hv = ((const float4*)hfeat)[(size_t)d * 32 + lane];
    float4 acc = make_float4(hv.x * ev, hv.y * ev, hv.z * ev, hv.w * ev);

    int i = beg;
    for (; i + 3 < end; i += 4) {
        int s0 = csr[i], s1 = csr[i + 1], s2 = csr[i + 2], s3 = csr[i + 3];
        float v0 = as_[s0 * H + myh] + adm;
        float v1 = as_[s1 * H + myh] + adm;
        float v2 = as_[s2 * H + myh] + adm;
        float v3 = as_[s3 * H + myh] + adm;
        v0 = v0 >= 0.f ? v0 : 0.2f * v0;
        v1 = v1 >= 0.f ? v1 : 0.2f * v1;
        v2 = v2 >= 0.f ? v2 : 0.2f * v2;
        v3 = v3 >= 0.f ? v3 : 0.2f * v3;
        float e0 = __expf(v0), e1 = __expf(v1), e2 = __expf(v2), e3 = __expf(v3);
        float4 g0 = ((const float4*)hfeat)[(size_t)s0 * 32 + lane];
        float4 g1 = ((const float4*)hfeat)[(size_t)s1 * 32 + lane];
        float4 g2 = ((const float4*)hfeat)[(size_t)s2 * 32 + lane];
        float4 g3 = ((const float4*)hfeat)[(size_t)s3 * 32 + lane];
        den += (e0 + e1) + (e2 + e3);
        acc.x += g0.x * e0 + g1.x * e1 + g2.x * e2 + g3.x * e3;
        acc.y += g0.y * e0 + g1.y * e1 + g2.y * e2 + g3.y * e3;
        acc.z += g0.z * e0 + g1.z * e1 + g2.z * e2 + g3.z * e3;
        acc.w += g0.w * e0 + g1.w * e1 + g2.w * e2 + g3.w * e3;
    }
    for (; i < end; i++) {
        int s0 = csr[i];
        float v0 = as_[s0 * H + myh] + adm;
        v0 = v0 >= 0.f ? v0 : 0.2f * v0;
        float e0 = __expf(v0);
        float4 g0 = ((const float4*)hfeat)[(size_t)s0 * 32 + lane];
        den += e0;
        acc.x += g0.x * e0;
        acc.y += g0.y * e0;
        acc.z += g0.z * e0;
        acc.w += g0.w * e0;
    }

    float inv = 1.f / (den + 1e-16f);
    float4 b = ((const float4*)bias)[lane];
    acc.x = acc.x * inv + b.x;
    acc.y = acc.y * inv + b.y;
    acc.z = acc.z * inv + b.z;
    acc.w = acc.w * inv + b.w;
    if (ELU) {
        acc.x = acc.x > 0.f ? acc.x : expm1f(acc.x);
        acc.y = acc.y > 0.f ? acc.y : expm1f(acc.y);
        acc.z = acc.z > 0.f ? acc.z : expm1f(acc.z);
        acc.w = acc.w > 0.f ? acc.w : expm1f(acc.w);
    }
    ((float4*)outp)[(size_t)d * 32 + lane] = acc;
}

// ---------------- launch ----------------
extern "C" void kernel_launch(void* const* d_in, const int* in_sizes, int n_in,
                              void* d_out, int out_size) {
    const float* x      = (const float*)d_in[0];
    const int*   ei     = (const int*)d_in[1];
    const float* W1     = (const float*)d_in[2];
    const float* a_src1 = (const float*)d_in[3];
    const float* a_dst1 = (const float*)d_in[4];
    const float* b1     = (const float*)d_in[5];
    const float* W2     = (const float*)d_in[6];
    const float* a_src2 = (const float*)d_in[7];
    const float* a_dst2 = (const float*)d_in[8];
    const float* b2     = (const float*)d_in[9];
    float* out = (float*)d_out;

    const int* src = ei;
    const int* dst = ei + NEDGES;

    float *p_h, *p_feat, *p_as, *p_ad;
    int *p_cnt, *p_rp, *p_cursor, *p_bsum, *p_csr;
    cudaGetSymbolAddress((void**)&p_h,      g_h);
    cudaGetSymbolAddress((void**)&p_feat,   g_feat);
    cudaGetSymbolAddress((void**)&p_as,     g_as);
    cudaGetSymbolAddress((void**)&p_ad,     g_ad);
    cudaGetSymbolAddress((void**)&p_cnt,    g_cnt);
    cudaGetSymbolAddress((void**)&p_rp,     g_rp);
    cudaGetSymbolAddress((void**)&p_cursor, g_cursor);
    cudaGetSymbolAddress((void**)&p_bsum,   g_bsum);
    cudaGetSymbolAddress((void**)&p_csr,    g_csr);

    // side stream + fork/join events (created once, on the uncaptured
    // correctness call; same node set is recorded on every capture)
    static cudaStream_t s_side = nullptr;
    static cudaEvent_t  ev_fork = nullptr, ev_join = nullptr;
    if (s_side == nullptr) {
        cudaStreamCreateWithFlags(&s_side, cudaStreamNonBlocking);
        cudaEventCreateWithFlags(&ev_fork, cudaEventDisableTiming);
        cudaEventCreateWithFlags(&ev_join, cudaEventDisableTiming);
    }

    const int NT = 256;
    int gemm_blocks  = (NNODES + 63) / 64;
    int node_warps   = (NNODES * 32 + NT - 1) / NT;
    int node1_blocks = (NNODES + 1 + NT - 1) / NT;
    int edge_blocks  = (NEDGES + NT - 1) / NT;
    int scan_blocks  = (NNODES + 4095) / 4096;

    // fork: CSR build runs on side stream, concurrent with GEMM1
    cudaEventRecord(ev_fork, 0);
    cudaStreamWaitEvent(s_side, ev_fork, 0);

    // main stream: GEMM1 (+alpha)
    gemm_alpha_kernel<4><<<gemm_blocks, NT>>>(x, W1, p_h, NNODES,
                                              a_src1, a_dst1, p_as, p_ad);

    // side stream: CSR build (shared by both layers)
    cudaMemsetAsync(p_cnt, 0, NNODES * sizeof(int), s_side);
    count_kernel<<<edge_blocks, NT, 0, s_side>>>(dst, p_cnt);
    scan_local_kernel<<<scan_blocks, 512, 0, s_side>>>(p_cnt, p_cnt, p_bsum);
    scan_add_kernel<<<node1_blocks, NT, 0, s_side>>>(p_cnt, p_bsum, p_rp, p_cursor, scan_blocks);
    scatter_kernel<<<edge_blocks, NT, 0, s_side>>>(src, dst, p_cursor, p_csr);
    cudaEventRecord(ev_join, s_side);

    // join
    cudaStreamWaitEvent(0, ev_join, 0);

    // Layer 1 aggregation (H=4) + ELU
    fused_agg_kernel<4, true><<<node_warps, NT>>>(p_rp, p_csr, p_as, p_ad, p_h, b1, p_feat);

    // Layer 2
    gemm_alpha_kernel<1><<<gemm_blocks, NT>>>(p_feat, W2, p_h, NNODES,
                                              a_src2, a_dst2, p_as, p_ad);
    fused_agg_kernel<1, false><<<node_warps, NT>>>(p_rp, p_csr, p_as, p_ad, p_h, b2, out);
}

// round 5
// speedup vs baseline: 4.2364x; 1.0442x over previous
#include <cuda_runtime.h>
#include <cuda_fp16.h>
#include <math.h>

#define NNODES 100000
#define NEDGES 1600000
#define FDIM   128

// ---------------- scratch ----------------
__device__ __half g_hh[NNODES * FDIM];   // GEMM output in fp16 (gather path)
__device__ float  g_feat[NNODES * FDIM]; // layer-1 activations (fp32, GEMM2 input)
__device__ float  g_as[NNODES * 4];
__device__ float  g_ad[NNODES * 4];
__device__ int    g_cnt[NNODES];
__device__ int    g_rp[NNODES + 1];
__device__ int    g_cursor[NNODES];
__device__ int    g_bsum[64];
__device__ int    g_csr[NEDGES];

// ---------------- f32x2 helpers (sm_103a packed fp32) ----------------
__device__ __forceinline__ unsigned long long pack2(float x) {
    unsigned long long r;
    asm("mov.b64 %0, {%1, %1};" : "=l"(r) : "r"(__float_as_uint(x)));
    return r;
}
#define FMA2(d, a, b) asm("fma.rn.f32x2 %0, %1, %2, %0;" : "+l"(d) : "l"(a), "l"(b))
__device__ __forceinline__ void unpack2(unsigned long long p, float& lo, float& hi) {
    asm("mov.b64 {%0, %1}, %2;" : "=f"(lo), "=f"(hi) : "l"(p));
}

// ---------------- GEMM + fused alpha epilogue; fp16 feature output ----------------
// hh[M,128] (fp16) = A[M,128] @ W[128,128]; as_/ad_ = per-head dots (fp32, exact).
template <int H>
__global__ void gemm_alpha_kernel(const float* __restrict__ A,
                                  const float* __restrict__ W,
                                  __half* __restrict__ hh, int M,
                                  const float* __restrict__ a_src,
                                  const float* __restrict__ a_dst,
                                  float* __restrict__ as_, float* __restrict__ ad_) {
    __shared__ float As[128 * 66];
    int tid  = threadIdx.x;
    int row0 = blockIdx.x * 64;
    int tx = tid & 31;   // col group: cols tx*4..tx*4+3
    int ty = tid >> 5;   // row group: rows ty*8..ty*8+7

    // load + transpose A tile
    #pragma unroll
    for (int i = 0; i < 8; i++) {
        int idx = tid + 256 * i;      // float4 index
        int r   = idx >> 5;
        int c4  = idx & 31;
        float4 v = make_float4(0.f, 0.f, 0.f, 0.f);
        if (row0 + r < M) v = ((const float4*)A)[(size_t)(row0 + r) * 32 + c4];
        int c = c4 * 4;
        As[(c + 0) * 66 + r] = v.x;
        As[(c + 1) * 66 + r] = v.y;
        As[(c + 2) * 66 + r] = v.z;
        As[(c + 3) * 66 + r] = v.w;
    }
    __syncthreads();

    unsigned long long acc[4][4];
    #pragma unroll
    for (int p = 0; p < 4; p++)
        #pragma unroll
        for (int c = 0; c < 4; c++) acc[p][c] = 0ull;

    const float* asbase = As + ty * 8;
    #pragma unroll 4
    for (int k = 0; k < 128; k++) {
        float4 w = __ldg(&((const float4*)(W + k * 128))[tx]);
        unsigned long long w0 = pack2(w.x), w1 = pack2(w.y),
                           w2 = pack2(w.z), w3 = pack2(w.w);
        const unsigned long long* ap =
            (const unsigned long long*)(asbase + k * 66);
        unsigned long long a0 = ap[0], a1 = ap[1], a2 = ap[2], a3 = ap[3];
        FMA2(acc[0][0], a0, w0); FMA2(acc[0][1], a0, w1);
        FMA2(acc[0][2], a0, w2); FMA2(acc[0][3], a0, w3);
        FMA2(acc[1][0], a1, w0); FMA2(acc[1][1], a1, w1);
        FMA2(acc[1][2], a1, w2); FMA2(acc[1][3], a1, w3);
        FMA2(acc[2][0], a2, w0); FMA2(acc[2][1], a2, w1);
        FMA2(acc[2][2], a2, w2); FMA2(acc[2][3], a2, w3);
        FMA2(acc[3][0], a3, w0); FMA2(acc[3][1], a3, w1);
        FMA2(acc[3][2], a3, w2); FMA2(acc[3][3], a3, w3);
    }

    // epilogue: unpack, fp16 store, fused alpha dots (fp32)
    float4 s4 = ((const float4*)a_src)[tx];
    float4 d4 = ((const float4*)a_dst)[tx];
    const int G = 32 / H;

    #pragma unroll
    for (int p = 0; p < 4; p++) {
        float lo[4], hi[4];
        #pragma unroll
        for (int c = 0; c < 4; c++) unpack2(acc[p][c], lo[c], hi[c]);

        #pragma unroll
        for (int half = 0; half < 2; half++) {
            float* v = half ? hi : lo;
            int row = row0 + ty * 8 + p * 2 + half;
            bool ok = row < M;
            if (ok) {
                __half2 h01 = __floats2half2_rn(v[0], v[1]);
                __half2 h23 = __floats2half2_rn(v[2], v[3]);
                uint2 pk;
                pk.x = *(unsigned int*)&h01;
                pk.y = *(unsigned int*)&h23;
                ((uint2*)hh)[(size_t)row * 32 + tx] = pk;
            }
            float s = v[0] * s4.x + v[1] * s4.y + v[2] * s4.z + v[3] * s4.w;
            float d = v[0] * d4.x + v[1] * d4.y + v[2] * d4.z + v[3] * d4.w;
            #pragma unroll
            for (int off = G / 2; off > 0; off >>= 1) {
                s += __shfl_xor_sync(0xffffffffu, s, off);
                d += __shfl_xor_sync(0xffffffffu, d, off);
            }
            if (ok && (tx & (G - 1)) == 0) {
                int hd = tx / G;
                as_[row * H + hd] = s;
                ad_[row * H + hd] = d;
            }
        }
    }
}

// ---------------- CSR construction ----------------
__global__ void count_kernel(const int* __restrict__ dst, int* __restrict__ cnt) {
    int e = blockIdx.x * blockDim.x + threadIdx.x;
    if (e < NEDGES) atomicAdd(&cnt[dst[e]], 1);
}

__global__ void scan_local_kernel(const int* __restrict__ cnt,
                                  int* __restrict__ excl, int* __restrict__ bsum) {
    __shared__ int sh[512];
    int t = threadIdx.x;
    int base = blockIdx.x * 4096 + t * 8;
    int v[8];
    int run = 0;
    #pragma unroll
    for (int j = 0; j < 8; j++) {
        int c = (base + j < NNODES) ? cnt[base + j] : 0;
        v[j] = run;
        run += c;
    }
    sh[t] = run;
    __syncthreads();
    for (int off = 1; off < 512; off <<= 1) {
        int x = (t >= off) ? sh[t - off] : 0;
        __syncthreads();
        sh[t] += x;
        __syncthreads();
    }
    int excl_t = sh[t] - run;
    if (t == 511) bsum[blockIdx.x] = sh[511];
    #pragma unroll
    for (int j = 0; j < 8; j++)
        if (base + j < NNODES) excl[base + j] = excl_t + v[j];
}

__global__ void scan_add_kernel(const int* __restrict__ excl, const int* __restrict__ bsum,
                                int* __restrict__ rp, int* __restrict__ cursor, int nb) {
    int i = blockIdx.x * blockDim.x + threadIdx.x;
    if (i <= NNODES) {
        int blk = i >> 12;
        int base = 0;
        for (int j = 0; j < nb; j++)
            if (j < blk) base += bsum[j];
        if (i < NNODES) {
            int v = excl[i] + base;
            rp[i] = v;
            cursor[i] = v;
        } else {
            rp[NNODES] = NEDGES;
        }
    }
}

__global__ void scatter_kernel(const int* __restrict__ src, const int* __restrict__ dst,
                               int* __restrict__ cursor, int* __restrict__ csr) {
    int e = blockIdx.x * blockDim.x + threadIdx.x;
    if (e >= NEDGES) return;
    int p = atomicAdd(&cursor[dst[e]], 1);
    csr[p] = src[e];
}

// ---------------- fused aggregation: single pass, one warp per dst node ----------------
// Features gathered in fp16 (halved L2 traffic); weights/accumulation fp32.
template <int H, bool ELU>
__global__ void fused_agg_kernel(const int* __restrict__ rowp, const int* __restrict__ csr,
                                 const float* __restrict__ as_, const float* __restrict__ ad_,
                                 const __half* __restrict__ hfeat,
                                 const float* __restrict__ bias,
                                 float* __restrict__ outp) {
    int d    = (blockIdx.x * blockDim.x + threadIdx.x) >> 5;
    int lane = threadIdx.x & 31;
    if (d >= NNODES) return;
    int beg = rowp[d], end = rowp[d + 1];

    const int G = 32 / H;
    const int myh = lane / G;
    float adm = ad_[d * H + myh];
    const uint2* hf = (const uint2*)hfeat;

    // self loop
    float sv = as_[d * H + myh] + adm;
    sv = sv >= 0.f ? sv : 0.2f * sv;
    float ev = __expf(sv);
    float den = ev;
    uint2 rs = hf[(size_t)d * 32 + lane];
    float2 f0 = __half22float2(*(__half2*)&rs.x);
    float2 f1 = __half22float2(*(__half2*)&rs.y);
    float4 acc = make_float4(f0.x * ev, f0.y * ev, f1.x * ev, f1.y * ev);

    int i = beg;
    for (; i + 3 < end; i += 4) {
        int s0 = csr[i], s1 = csr[i + 1], s2 = csr[i + 2], s3 = csr[i + 3];
        float v0 = as_[s0 * H + myh] + adm;
        float v1 = as_[s1 * H + myh] + adm;
        float v2 = as_[s2 * H + myh] + adm;
        float v3 = as_[s3 * H + myh] + adm;
        v0 = v0 >= 0.f ? v0 : 0.2f * v0;
        v1 = v1 >= 0.f ? v1 : 0.2f * v1;
        v2 = v2 >= 0.f ? v2 : 0.2f * v2;
        v3 = v3 >= 0.f ? v3 : 0.2f * v3;
        float e0 = __expf(v0), e1 = __expf(v1), e2 = __expf(v2), e3 = __expf(v3);
        uint2 r0 = hf[(size_t)s0 * 32 + lane];
        uint2 r1 = hf[(size_t)s1 * 32 + lane];
        uint2 r2 = hf[(size_t)s2 * 32 + lane];
        uint2 r3 = hf[(size_t)s3 * 32 + lane];
        den += (e0 + e1) + (e2 + e3);
        float2 a0 = __half22float2(*(__half2*)&r0.x), b0 = __half22float2(*(__half2*)&r0.y);
        float2 a1 = __half22float2(*(__half2*)&r1.x), b1 = __half22float2(*(__half2*)&r1.y);
        float2 a2 = __half22float2(*(__half2*)&r2.x), b2 = __half22float2(*(__half2*)&r2.y);
        float2 a3 = __half22float2(*(__half2*)&r3.x), b3 = __half22float2(*(__half2*)&r3.y);
        acc.x += a0.x * e0 + a1.x * e1 + a2.x * e2 + a3.x * e3;
        acc.y += a0.y * e0 + a1.y * e1 + a2.y * e2 + a3.y * e3;
        acc.z += b0.x * e0 + b1.x * e1 + b2.x * e2 + b3.x * e3;
        acc.w += b0.y * e0 + b1.y * e1 + b2.y * e2 + b3.y * e3;
    }
    for (; i < end; i++) {
        int s0 = csr[i];
        float v0 = as_[s0 * H + myh] + adm;
        v0 = v0 >= 0.f ? v0 : 0.2f * v0;
        float e0 = __expf(v0);
        uint2 r0 = hf[(size_t)s0 * 32 + lane];
        float2 a0 = __half22float2(*(__half2*)&r0.x), b0 = __half22float2(*(__half2*)&r0.y);
        den += e0;
        acc.x += a0.x * e0;
        acc.y += a0.y * e0;
        acc.z += b0.x * e0;
        acc.w += b0.y * e0;
    }

    float inv = 1.f / (den + 1e-16f);
    float4 b = ((const float4*)bias)[lane];
    acc.x = acc.x * inv + b.x;
    acc.y = acc.y * inv + b.y;
    acc.z = acc.z * inv + b.z;
    acc.w = acc.w * inv + b.w;
    if (ELU) {
        acc.x = acc.x > 0.f ? acc.x : expm1f(acc.x);
        acc.y = acc.y > 0.f ? acc.y : expm1f(acc.y);
        acc.z = acc.z > 0.f ? acc.z : expm1f(acc.z);
        acc.w = acc.w > 0.f ? acc.w : expm1f(acc.w);
    }
    ((float4*)outp)[(size_t)d * 32 + lane] = acc;
}

// ---------------- launch ----------------
extern "C" void kernel_launch(void* const* d_in, const int* in_sizes, int n_in,
                              void* d_out, int out_size) {
    const float* x      = (const float*)d_in[0];
    const int*   ei     = (const int*)d_in[1];
    const float* W1     = (const float*)d_in[2];
    const float* a_src1 = (const float*)d_in[3];
    const float* a_dst1 = (const float*)d_in[4];
    const float* b1     = (const float*)d_in[5];
    const float* W2     = (const float*)d_in[6];
    const float* a_src2 = (const float*)d_in[7];
    const float* a_dst2 = (const float*)d_in[8];
    const float* b2     = (const float*)d_in[9];
    float* out = (float*)d_out;

    const int* src = ei;
    const int* dst = ei + NEDGES;

    __half* p_hh;
    float *p_feat, *p_as, *p_ad;
    int *p_cnt, *p_rp, *p_cursor, *p_bsum, *p_csr;
    cudaGetSymbolAddress((void**)&p_hh,     g_hh);
    cudaGetSymbolAddress((void**)&p_feat,   g_feat);
    cudaGetSymbolAddress((void**)&p_as,     g_as);
    cudaGetSymbolAddress((void**)&p_ad,     g_ad);
    cudaGetSymbolAddress((void**)&p_cnt,    g_cnt);
    cudaGetSymbolAddress((void**)&p_rp,     g_rp);
    cudaGetSymbolAddress((void**)&p_cursor, g_cursor);
    cudaGetSymbolAddress((void**)&p_bsum,   g_bsum);
    cudaGetSymbolAddress((void**)&p_csr,    g_csr);

    static cudaStream_t s_side = nullptr;
    static cudaEvent_t  ev_fork = nullptr, ev_join = nullptr;
    if (s_side == nullptr) {
        cudaStreamCreateWithFlags(&s_side, cudaStreamNonBlocking);
        cudaEventCreateWithFlags(&ev_fork, cudaEventDisableTiming);
        cudaEventCreateWithFlags(&ev_join, cudaEventDisableTiming);
    }

    const int NT = 256;
    int gemm_blocks  = (NNODES + 63) / 64;
    int node_warps   = (NNODES * 32 + NT - 1) / NT;
    int node1_blocks = (NNODES + 1 + NT - 1) / NT;
    int edge_blocks  = (NEDGES + NT - 1) / NT;
    int scan_blocks  = (NNODES + 4095) / 4096;

    // fork: CSR build on side stream, concurrent with GEMM1
    cudaEventRecord(ev_fork, 0);
    cudaStreamWaitEvent(s_side, ev_fork, 0);

    gemm_alpha_kernel<4><<<gemm_blocks, NT>>>(x, W1, p_hh, NNODES,
                                              a_src1, a_dst1, p_as, p_ad);

    cudaMemsetAsync(p_cnt, 0, NNODES * sizeof(int), s_side);
    count_kernel<<<edge_blocks, NT, 0, s_side>>>(dst, p_cnt);
    scan_local_kernel<<<scan_blocks, 512, 0, s_side>>>(p_cnt, p_cnt, p_bsum);
    scan_add_kernel<<<node1_blocks, NT, 0, s_side>>>(p_cnt, p_bsum, p_rp, p_cursor, scan_blocks);
    scatter_kernel<<<edge_blocks, NT, 0, s_side>>>(src, dst, p_cursor, p_csr);
    cudaEventRecord(ev_join, s_side);
    cudaStreamWaitEvent(0, ev_join, 0);

    fused_agg_kernel<4, true><<<node_warps, NT>>>(p_rp, p_csr, p_as, p_ad, p_hh, b1, p_feat);

    gemm_alpha_kernel<1><<<gemm_blocks, NT>>>(p_feat, W2, p_hh, NNODES,
                                              a_src2, a_dst2, p_as, p_ad);
    fused_agg_kernel<1, false><<<node_warps, NT>>>(p_rp, p_csr, p_as, p_ad, p_hh, b2, out);
}